// round 1
// baseline (speedup 1.0000x reference)
#include <cuda_runtime.h>

// ---------------------------------------------------------------------------
// DataReUploadingLinear: 6-qubit data re-uploading circuit.
//   H[b] = sum_p x[b,p] * Pauli_p  (4000 coeffs, padded to 4096)
//   Ud[b] = expm(-i H[b]); Up[r] = expm(-i sum_p w[r,p] Pauli_{p+1})
//   psi = Up[3] Ud Up[2] Ud Up[1] Ud Up[0] Ud |0>
//   out[b,k] = |psi_k|^2 + bias[k]
//
// Strategy:
//   * H built via per-xmask Walsh-Hadamard transform (64-pt WHT per m).
//   * expm by scaling-squaring (s=8) + Paterson-Stockmeyer Taylor deg 15:
//     14 complex 64x64x64 matmuls per matrix, all in shared memory.
//   * One CTA per sample (512 CTAs); a 4-CTA pre-kernel builds Up matrices.
// ---------------------------------------------------------------------------

#define DIM      64
#define NPAULI   4096
#define STRIDE   65                  // smem row stride (conflict mitigation)
#define PL       (64 * STRIDE)       // plane size in floats
#define NTHREADS 256
#define INV_SCALE (1.0f / 256.0f)    // 1 / 2^s, s = 8

__device__ float2 g_Up[4][DIM * DIM];   // parameter unitaries, row-major [i*64+k]

// Z = [Gj(A)] + X*Y   (complex, all smem planes, 64x64, stride STRIDE)
// Gj = c0*I + c1*A + c2*A2 + c3*A3 (elementwise init of accumulator).
template <bool WITHG>
__device__ __forceinline__ void cmm(
    const float* __restrict__ Xr, const float* __restrict__ Xi,
    const float* __restrict__ Yr, const float* __restrict__ Yi,
    float* __restrict__ Zr, float* __restrict__ Zi,
    const float* __restrict__ Ar, const float* __restrict__ Ai,
    const float* __restrict__ A2r, const float* __restrict__ A2i,
    const float* __restrict__ A3r, const float* __restrict__ A3i,
    float c0, float c1, float c2, float c3)
{
    const int tid = threadIdx.x;
    const int ty = tid >> 4, tx = tid & 15;
    const int i0 = ty * 4, j0 = tx * 4;

    float cr[4][4], ci[4][4];
#pragma unroll
    for (int a = 0; a < 4; a++)
#pragma unroll
        for (int b = 0; b < 4; b++) {
            if (WITHG) {
                const int i = i0 + a, j = j0 + b;
                const int o = i * STRIDE + j;
                float gr = c1 * Ar[o] + c2 * A2r[o] + c3 * A3r[o];
                float gi = c1 * Ai[o] + c2 * A2i[o] + c3 * A3i[o];
                if (i == j) gr += c0;
                cr[a][b] = gr; ci[a][b] = gi;
            } else {
                cr[a][b] = 0.f; ci[a][b] = 0.f;
            }
        }

#pragma unroll 2
    for (int k = 0; k < 64; k++) {
        float xr[4], xi[4], yr[4], yi[4];
#pragma unroll
        for (int a = 0; a < 4; a++) {
            xr[a] = Xr[(i0 + a) * STRIDE + k];
            xi[a] = Xi[(i0 + a) * STRIDE + k];
        }
#pragma unroll
        for (int b = 0; b < 4; b++) {
            yr[b] = Yr[k * STRIDE + j0 + b];
            yi[b] = Yi[k * STRIDE + j0 + b];
        }
#pragma unroll
        for (int a = 0; a < 4; a++)
#pragma unroll
            for (int b = 0; b < 4; b++) {
                cr[a][b] = fmaf(xr[a], yr[b], cr[a][b]);
                cr[a][b] = fmaf(-xi[a], yi[b], cr[a][b]);
                ci[a][b] = fmaf(xr[a], yi[b], ci[a][b]);
                ci[a][b] = fmaf(xi[a], yr[b], ci[a][b]);
            }
    }

#pragma unroll
    for (int a = 0; a < 4; a++)
#pragma unroll
        for (int b = 0; b < 4; b++) {
            Zr[(i0 + a) * STRIDE + j0 + b] = cr[a][b];
            Zi[(i0 + a) * STRIDE + j0 + b] = ci[a][b];
        }
}

// mode 0: blockIdx = r in [0,4): build Up[r] from weight, store to g_Up.
// mode 1: blockIdx = b in [0,512): build Ud, run the 4-rep circuit, write out.
__global__ __launch_bounds__(NTHREADS)
void qreup_kernel(const float* __restrict__ x,
                  const float* __restrict__ weight,
                  const float* __restrict__ bias,
                  float* __restrict__ out,
                  int mode)
{
    extern __shared__ float sm[];
    float* Ar  = sm + 0 * PL;  float* Ai  = sm + 1 * PL;
    float* A2r = sm + 2 * PL;  float* A2i = sm + 3 * PL;
    float* A3r = sm + 4 * PL;  float* A3i = sm + 5 * PL;
    float* P4r = sm + 6 * PL;  float* P4i = sm + 7 * PL;
    float* Br  = sm + 8 * PL;  float* Bi  = sm + 9 * PL;
    float* Cr  = sm + 10 * PL; float* Ci  = sm + 11 * PL;

    const int tid = threadIdx.x;
    const int blk = blockIdx.x;

    // ---- 1. Pauli coefficients (padded to 4096) into Br[0..4095] ----
    if (mode == 1) {
        const float* xrow = x + (size_t)blk * 4000;
        for (int p = tid; p < NPAULI; p += NTHREADS)
            Br[p] = (p < 4000) ? xrow[p] : 0.f;
    } else {
        const float* wrow = weight + (size_t)blk * (NPAULI - 1);
        for (int p = tid; p < NPAULI; p += NTHREADS)
            Br[p] = (p == 0) ? 0.f : wrow[p - 1];   // identity Pauli excluded
    }
    __syncthreads();

    // ---- 2. D[m][t] = coef(p(m,t)) * (-i)^popc(t&m) into C planes ----
    // digit_k = 2*t_k + (m_k ^ t_k)  ->  p = morton(m^t, t)
    for (int idx = tid; idx < NPAULI; idx += NTHREADS) {
        const int m = idx >> 6, t = idx & 63;
        const int mt = m ^ t;
        int p = 0;
#pragma unroll
        for (int k = 0; k < 6; k++)
            p |= (((mt >> k) & 1) << (2 * k)) | (((t >> k) & 1) << (2 * k + 1));
        const float v = Br[p];
        const int c = __popc(t & m) & 3;        // (-i)^c
        float re, im;
        switch (c) {
            case 0:  re =  v; im = 0.f; break;
            case 1:  re = 0.f; im = -v; break;
            case 2:  re = -v; im = 0.f; break;
            default: re = 0.f; im =  v; break;
        }
        Cr[idx] = re; Ci[idx] = im;
    }
    __syncthreads();

    // ---- 3. 64-pt WHT over t for each m: W[m][i] = sum_t D (-1)^popc(t&i) ----
    for (int s = 0; s < 6; s++) {
        const int half = 1 << s;
        for (int n = tid; n < 2048; n += NTHREADS) {
            const int m = n >> 5, r = n & 31;
            const int t0 = ((r >> s) << (s + 1)) | (r & (half - 1));
            const int a0 = m * 64 + t0, a1 = a0 + half;
            const float ur = Cr[a0], ui = Ci[a0];
            const float vr = Cr[a1], vi = Ci[a1];
            Cr[a0] = ur + vr; Ci[a0] = ui + vi;
            Cr[a1] = ur - vr; Ci[a1] = ui - vi;
        }
        __syncthreads();
    }

    // ---- 4. A = -i*H/2^s :  H[i][i^m] = W[m][i] ----
    for (int idx = tid; idx < NPAULI; idx += NTHREADS) {
        const int m = idx >> 6, i = idx & 63;
        const int j = i ^ m;
        const float hr = Cr[m * 64 + i], hi = Ci[m * 64 + i];
        Ar[i * STRIDE + j] =  hi * INV_SCALE;   // -i*(hr + i*hi) = hi - i*hr
        Ai[i * STRIDE + j] = -hr * INV_SCALE;
    }
    __syncthreads();

    // ---- 5. powers: A2, A3, P4 = A2*A2 ----
    cmm<false>(Ar, Ai, Ar, Ai, A2r, A2i, Ar, Ai, A2r, A2i, A3r, A3i, 0, 0, 0, 0);
    __syncthreads();
    cmm<false>(Ar, Ai, A2r, A2i, A3r, A3i, Ar, Ai, A2r, A2i, A3r, A3i, 0, 0, 0, 0);
    __syncthreads();
    cmm<false>(A2r, A2i, A2r, A2i, P4r, P4i, Ar, Ai, A2r, A2i, A3r, A3i, 0, 0, 0, 0);
    __syncthreads();

    // ---- 6. Taylor deg-15 PS: E = G0 + P4*(G1 + P4*(G2 + P4*G3)) ----
    {   // B = G3 elementwise: 1/12! ... 1/15!
        const float c0 = 2.08767570e-9f, c1 = 1.60590438e-10f;
        const float c2 = 1.14707456e-11f, c3 = 7.64716373e-13f;
        for (int idx = tid; idx < NPAULI; idx += NTHREADS) {
            const int i = idx >> 6, j = idx & 63;
            const int o = i * STRIDE + j;
            float gr = c1 * Ar[o] + c2 * A2r[o] + c3 * A3r[o];
            float gi = c1 * Ai[o] + c2 * A2i[o] + c3 * A3i[o];
            if (i == j) gr += c0;
            Br[o] = gr; Bi[o] = gi;
        }
    }
    __syncthreads();
    // C = G2 + P4*B   (1/8!..1/11!)
    cmm<true>(P4r, P4i, Br, Bi, Cr, Ci, Ar, Ai, A2r, A2i, A3r, A3i,
              2.48015876e-5f, 2.75573196e-6f, 2.75573196e-7f, 2.50521084e-8f);
    __syncthreads();
    // B = G1 + P4*C   (1/4!..1/7!)
    cmm<true>(P4r, P4i, Cr, Ci, Br, Bi, Ar, Ai, A2r, A2i, A3r, A3i,
              1.f / 24.f, 1.f / 120.f, 1.f / 720.f, 1.f / 5040.f);
    __syncthreads();
    // C = G0 + P4*B   (1, 1, 1/2, 1/6)
    cmm<true>(P4r, P4i, Br, Bi, Cr, Ci, Ar, Ai, A2r, A2i, A3r, A3i,
              1.f, 1.f, 0.5f, 1.f / 6.f);
    __syncthreads();

    // ---- 7. 8 squarings (ping-pong C <-> B); result lands in C ----
    float *qr = Cr, *qi = Ci, *or_ = Br, *oi = Bi;
#pragma unroll 1
    for (int q = 0; q < 8; q++) {
        cmm<false>(qr, qi, qr, qi, or_, oi, Ar, Ai, A2r, A2i, A3r, A3i, 0, 0, 0, 0);
        __syncthreads();
        float* t;
        t = qr; qr = or_; or_ = t;
        t = qi; qi = oi;  oi  = t;
    }
    // U = (qr, qi)

    if (mode == 0) {
        for (int idx = tid; idx < DIM * DIM; idx += NTHREADS) {
            const int i = idx >> 6, j = idx & 63;
            g_Up[blk][idx] = make_float2(qr[i * STRIDE + j], qi[i * STRIDE + j]);
        }
        return;
    }

    // ---- 8. circuit: psi = (Up[r] * Ud)^{r=0..3} |0> ----
    __shared__ float2 psiA[DIM], psiB[DIM];
    if (tid < DIM) psiA[tid] = make_float2(tid == 0 ? 1.f : 0.f, 0.f);
    __syncthreads();

    float2* pin = psiA;
    float2* pout = psiB;
    const int row = tid >> 2, part = tid & 3;

    for (int r = 0; r < 4; r++) {
        // pout = Ud * pin
        {
            float sr = 0.f, si = 0.f;
            const int k0 = part * 16;
#pragma unroll
            for (int k = k0; k < k0 + 16; k++) {
                const float mr = qr[row * STRIDE + k], mi = qi[row * STRIDE + k];
                const float2 v = pin[k];
                sr = fmaf(mr, v.x, sr); sr = fmaf(-mi, v.y, sr);
                si = fmaf(mr, v.y, si); si = fmaf(mi, v.x, si);
            }
            sr += __shfl_xor_sync(0xffffffffu, sr, 1);
            sr += __shfl_xor_sync(0xffffffffu, sr, 2);
            si += __shfl_xor_sync(0xffffffffu, si, 1);
            si += __shfl_xor_sync(0xffffffffu, si, 2);
            if (part == 0) pout[row] = make_float2(sr, si);
        }
        __syncthreads();
        { float2* t = pin; pin = pout; pout = t; }

        // pout = Up[r] * pin
        {
            const float2* U = g_Up[r];
            float sr = 0.f, si = 0.f;
            const int k0 = part * 16;
#pragma unroll
            for (int k = k0; k < k0 + 16; k++) {
                const float2 u = U[row * 64 + k];
                const float2 v = pin[k];
                sr = fmaf(u.x, v.x, sr); sr = fmaf(-u.y, v.y, sr);
                si = fmaf(u.x, v.y, si); si = fmaf(u.y, v.x, si);
            }
            sr += __shfl_xor_sync(0xffffffffu, sr, 1);
            sr += __shfl_xor_sync(0xffffffffu, sr, 2);
            si += __shfl_xor_sync(0xffffffffu, si, 1);
            si += __shfl_xor_sync(0xffffffffu, si, 2);
            if (part == 0) pout[row] = make_float2(sr, si);
        }
        __syncthreads();
        { float2* t = pin; pin = pout; pout = t; }
    }

    if (tid < DIM) {
        const float2 v = pin[tid];
        out[(size_t)blk * DIM + tid] = fmaf(v.x, v.x, v.y * v.y) + bias[tid];
    }
}

extern "C" void kernel_launch(void* const* d_in, const int* in_sizes, int n_in,
                              void* d_out, int out_size)
{
    const float* x      = (const float*)d_in[0];   // [512, 4000]
    const float* weight = (const float*)d_in[1];   // [4, 4095]
    const float* bias   = (const float*)d_in[2];   // [64]
    float* out = (float*)d_out;                    // [512, 64]

    const int B     = in_sizes[0] / 4000;
    const int nreps = in_sizes[1] / (NPAULI - 1);

    const size_t smem = (size_t)12 * PL * sizeof(float);   // 199,680 B
    cudaFuncSetAttribute(qreup_kernel,
                         cudaFuncAttributeMaxDynamicSharedMemorySize, (int)smem);

    qreup_kernel<<<nreps, NTHREADS, smem>>>(x, weight, bias, out, 0);
    qreup_kernel<<<B,     NTHREADS, smem>>>(x, weight, bias, out, 1);
}

// round 3
// speedup vs baseline: 1.5892x; 1.5892x over previous
#include <cuda_runtime.h>

// ---------------------------------------------------------------------------
// DataReUploadingLinear: 6-qubit data re-uploading circuit.
//   Round 2: f32x2 packed FMA mainloop, stride-68 LDS.128 layout,
//   degree-11 Paterson-Stockmeyer (13 matmuls), fused Up/Ud build kernel
//   + tiny circuit kernel.
// ---------------------------------------------------------------------------

#define DIM      64
#define NPAULI   4096
#define S        68                  // smem row stride (17 x float4, 16B-aligned rows)
#define PL       (64 * S)            // plane size in floats (4352)
#define NTHREADS 256
#define INV_SCALE (1.0f / 256.0f)    // 1 / 2^s, s = 8
#define MAXB     512

typedef unsigned long long u64;

__device__ float2 g_Up[4][DIM * DIM];      // parameter unitaries [i*64+k]
__device__ float2 g_Ud[MAXB][DIM * DIM];   // per-sample data unitaries

__device__ __forceinline__ u64 pk2(float lo, float hi) {
    u64 r; asm("mov.b64 %0, {%1, %2};" : "=l"(r) : "f"(lo), "f"(hi)); return r;
}
__device__ __forceinline__ u64 f2fma(u64 a, u64 b, u64 c) {
    u64 d; asm("fma.rn.f32x2 %0, %1, %2, %3;" : "=l"(d) : "l"(a), "l"(b), "l"(c));
    return d;
}

// Z = [G(A)] + X*Y, complex 64x64 in smem (separate re/im planes, stride S).
// G = c0*I + c1*A + c2*A2 when WITHG. f32x2-packed over output column pairs.
template <bool WITHG>
__device__ __forceinline__ void cmm(
    const float* __restrict__ Xr, const float* __restrict__ Xi,
    const float* __restrict__ Yr, const float* __restrict__ Yi,
    float* __restrict__ Zr, float* __restrict__ Zi,
    const float* __restrict__ Ar, const float* __restrict__ Ai,
    const float* __restrict__ A2r, const float* __restrict__ A2i,
    float c0, float c1, float c2)
{
    const int tid = threadIdx.x;
    const int ty = tid >> 4, tx = tid & 15;
    const int i0 = ty * 4, j0 = tx * 4;

    u64 cr[4][2], ci[4][2];
#pragma unroll
    for (int a = 0; a < 4; a++)
#pragma unroll
        for (int p = 0; p < 2; p++) {
            if (WITHG) {
                const int i = i0 + a, j = j0 + 2 * p;
                const int o0 = i * S + j, o1 = o0 + 1;
                float g0r = c1 * Ar[o0] + c2 * A2r[o0] + ((i == j)     ? c0 : 0.f);
                float g1r = c1 * Ar[o1] + c2 * A2r[o1] + ((i == j + 1) ? c0 : 0.f);
                float g0i = c1 * Ai[o0] + c2 * A2i[o0];
                float g1i = c1 * Ai[o1] + c2 * A2i[o1];
                cr[a][p] = pk2(g0r, g1r);
                ci[a][p] = pk2(g0i, g1i);
            } else {
                cr[a][p] = 0ull; ci[a][p] = 0ull;
            }
        }

#pragma unroll 2
    for (int k0 = 0; k0 < 64; k0 += 2) {
        // X: broadcast loads, vectorized over k (LDS.64)
        float2 xr2[4], xi2[4];
#pragma unroll
        for (int a = 0; a < 4; a++) {
            xr2[a] = *(const float2*)&Xr[(i0 + a) * S + k0];
            xi2[a] = *(const float2*)&Xi[(i0 + a) * S + k0];
        }
        // Y: LDS.128, reinterpreted directly as packed f32x2 column pairs
        u64 yr[2][2], yi[2][2];
#pragma unroll
        for (int kk = 0; kk < 2; kk++) {
            const ulonglong2 r2 = *(const ulonglong2*)&Yr[(k0 + kk) * S + j0];
            const ulonglong2 q2 = *(const ulonglong2*)&Yi[(k0 + kk) * S + j0];
            yr[kk][0] = r2.x; yr[kk][1] = r2.y;
            yi[kk][0] = q2.x; yi[kk][1] = q2.y;
        }
#pragma unroll
        for (int kk = 0; kk < 2; kk++)
#pragma unroll
            for (int a = 0; a < 4; a++) {
                const float xr = kk ? xr2[a].y : xr2[a].x;
                const float xi = kk ? xi2[a].y : xi2[a].x;
                const u64 xrr = pk2(xr, xr);
                const u64 xnn = pk2(-xi, -xi);
                const u64 xii = pk2(xi, xi);
#pragma unroll
                for (int p = 0; p < 2; p++) {
                    cr[a][p] = f2fma(xrr, yr[kk][p], cr[a][p]);
                    cr[a][p] = f2fma(xnn, yi[kk][p], cr[a][p]);
                    ci[a][p] = f2fma(xrr, yi[kk][p], ci[a][p]);
                    ci[a][p] = f2fma(xii, yr[kk][p], ci[a][p]);
                }
            }
    }

#pragma unroll
    for (int a = 0; a < 4; a++)
#pragma unroll
        for (int p = 0; p < 2; p++) {
            *(u64*)&Zr[(i0 + a) * S + j0 + 2 * p] = cr[a][p];
            *(u64*)&Zi[(i0 + a) * S + j0 + 2 * p] = ci[a][p];
        }
}

// Build one expm: blockIdx < nreps -> Up[blk] from weight; else Ud[blk-nreps].
__global__ __launch_bounds__(NTHREADS)
void build_kernel(const float* __restrict__ x,
                  const float* __restrict__ weight,
                  int nreps)
{
    extern __shared__ float sm[];
    float* Ar  = sm + 0 * PL;  float* Ai  = sm + 1 * PL;
    float* A2r = sm + 2 * PL;  float* A2i = sm + 3 * PL;
    float* A3r = sm + 4 * PL;  float* A3i = sm + 5 * PL;
    float* Br  = sm + 6 * PL;  float* Bi  = sm + 7 * PL;
    float* Cr  = sm + 8 * PL;  float* Ci  = sm + 9 * PL;

    const int tid = threadIdx.x;
    const int blk = blockIdx.x;
    const bool is_param = (blk < nreps);

    // ---- 1. Pauli coefficients (padded to 4096) into Br[0..4095] ----
    if (is_param) {
        const float* wrow = weight + (size_t)blk * (NPAULI - 1);
        for (int p = tid; p < NPAULI; p += NTHREADS)
            Br[p] = (p == 0) ? 0.f : wrow[p - 1];      // identity excluded
    } else {
        const float* xrow = x + (size_t)(blk - nreps) * 4000;
        for (int p = tid; p < NPAULI; p += NTHREADS)
            Br[p] = (p < 4000) ? xrow[p] : 0.f;
    }
    __syncthreads();

    // ---- 2. D[m][t] = coef(p(m,t)) * (-i)^popc(t&m) ----
    for (int idx = tid; idx < NPAULI; idx += NTHREADS) {
        const int m = idx >> 6, t = idx & 63;
        const int mt = m ^ t;
        int p = 0;
#pragma unroll
        for (int k = 0; k < 6; k++)
            p |= (((mt >> k) & 1) << (2 * k)) | (((t >> k) & 1) << (2 * k + 1));
        const float v = Br[p];
        const int c = __popc(t & m) & 3;   // (-i)^c
        float re, im;
        switch (c) {
            case 0:  re =  v; im = 0.f; break;
            case 1:  re = 0.f; im = -v; break;
            case 2:  re = -v; im = 0.f; break;
            default: re = 0.f; im =  v; break;
        }
        Cr[idx] = re; Ci[idx] = im;
    }
    __syncthreads();

    // ---- 3. 64-pt WHT over t for each m ----
    for (int s = 0; s < 6; s++) {
        const int half = 1 << s;
        for (int n = tid; n < 2048; n += NTHREADS) {
            const int m = n >> 5, r = n & 31;
            const int t0 = ((r >> s) << (s + 1)) | (r & (half - 1));
            const int a0 = m * 64 + t0, a1 = a0 + half;
            const float ur = Cr[a0], ui = Ci[a0];
            const float vr = Cr[a1], vi = Ci[a1];
            Cr[a0] = ur + vr; Ci[a0] = ui + vi;
            Cr[a1] = ur - vr; Ci[a1] = ui - vi;
        }
        __syncthreads();
    }

    // ---- 4. A = -i*H/2^s :  H[i][i^m] = W[m][i] ----
    for (int idx = tid; idx < NPAULI; idx += NTHREADS) {
        const int m = idx >> 6, i = idx & 63;
        const int j = i ^ m;
        const float hr = Cr[m * 64 + i], hi = Ci[m * 64 + i];
        Ar[i * S + j] =  hi * INV_SCALE;   // -i*(hr+i*hi) = hi - i*hr
        Ai[i * S + j] = -hr * INV_SCALE;
    }
    __syncthreads();

    // ---- 5. powers A2, A3 ----
    cmm<false>(Ar, Ai, Ar, Ai, A2r, A2i, Ar, Ai, A2r, A2i, 0, 0, 0);
    __syncthreads();
    cmm<false>(A2r, A2i, Ar, Ai, A3r, A3i, Ar, Ai, A2r, A2i, 0, 0, 0);
    __syncthreads();

    // ---- 6. degree-11 PS: E = G0 + A3*(G1 + A3*(G2 + A3*G3)) ----
    {   // B = G3 = I/9! + A/10! + A2/11!
        const float c0 = 2.75573192e-6f, c1 = 2.75573192e-7f, c2 = 2.50521084e-8f;
        for (int idx = tid; idx < NPAULI; idx += NTHREADS) {
            const int i = idx >> 6, j = idx & 63;
            const int o = i * S + j;
            float gr = c1 * Ar[o] + c2 * A2r[o];
            float gi = c1 * Ai[o] + c2 * A2i[o];
            if (i == j) gr += c0;
            Br[o] = gr; Bi[o] = gi;
        }
    }
    __syncthreads();
    // C = G2 + A3*B   (I/6! + A/7! + A2/8!)
    cmm<true>(A3r, A3i, Br, Bi, Cr, Ci, Ar, Ai, A2r, A2i,
              1.38888889e-3f, 1.98412698e-4f, 2.48015873e-5f);
    __syncthreads();
    // B = G1 + A3*C   (I/3! + A/4! + A2/5!)
    cmm<true>(A3r, A3i, Cr, Ci, Br, Bi, Ar, Ai, A2r, A2i,
              1.f / 6.f, 1.f / 24.f, 1.f / 120.f);
    __syncthreads();
    // C = G0 + A3*B   (I + A + A2/2)
    cmm<true>(A3r, A3i, Br, Bi, Cr, Ci, Ar, Ai, A2r, A2i,
              1.f, 1.f, 0.5f);
    __syncthreads();

    // ---- 7. 8 squarings, ping-pong C <-> B (even count -> ends in C) ----
    float *qr = Cr, *qi = Ci, *pr = Br, *pi = Bi;
#pragma unroll 1
    for (int q = 0; q < 8; q++) {
        cmm<false>(qr, qi, qr, qi, pr, pi, Ar, Ai, A2r, A2i, 0, 0, 0);
        __syncthreads();
        float* t;
        t = qr; qr = pr; pr = t;
        t = qi; qi = pi; pi = t;
    }

    // ---- 8. store U to global ----
    float2* dst = is_param ? g_Up[blk] : g_Ud[blk - nreps];
    for (int idx = tid; idx < DIM * DIM; idx += NTHREADS) {
        const int i = idx >> 6, j = idx & 63;
        dst[idx] = make_float2(qr[i * S + j], qi[i * S + j]);
    }
}

// Apply the circuit: psi = prod_r (Up[r] * Ud[b]) |0>;  out = |psi|^2 + bias.
__global__ __launch_bounds__(NTHREADS)
void circuit_kernel(const float* __restrict__ bias,
                    float* __restrict__ out, int nreps)
{
    __shared__ float2 Usm[DIM * DIM];
    __shared__ float2 psiA[DIM], psiB[DIM];

    const int tid = threadIdx.x;
    const int b = blockIdx.x;

    const float2* Ud = g_Ud[b];
    for (int idx = tid; idx < DIM * DIM; idx += NTHREADS)
        Usm[idx] = Ud[idx];
    if (tid < DIM) psiA[tid] = make_float2(tid == 0 ? 1.f : 0.f, 0.f);
    __syncthreads();

    float2* pin = psiA;
    float2* pout = psiB;
    const int row = tid >> 2, part = tid & 3;
    const int k0 = part * 16;

    for (int r = 0; r < nreps; r++) {
        {   // pout = Ud * pin
            float sr = 0.f, si = 0.f;
#pragma unroll
            for (int k = k0; k < k0 + 16; k++) {
                const float2 u = Usm[row * DIM + k];
                const float2 v = pin[k];
                sr = fmaf(u.x, v.x, sr); sr = fmaf(-u.y, v.y, sr);
                si = fmaf(u.x, v.y, si); si = fmaf(u.y, v.x, si);
            }
            sr += __shfl_xor_sync(0xffffffffu, sr, 1);
            sr += __shfl_xor_sync(0xffffffffu, sr, 2);
            si += __shfl_xor_sync(0xffffffffu, si, 1);
            si += __shfl_xor_sync(0xffffffffu, si, 2);
            if (part == 0) pout[row] = make_float2(sr, si);
        }
        __syncthreads();
        { float2* t = pin; pin = pout; pout = t; }

        {   // pout = Up[r] * pin
            const float2* U = g_Up[r];
            float sr = 0.f, si = 0.f;
#pragma unroll
            for (int k = k0; k < k0 + 16; k++) {
                const float2 u = U[row * DIM + k];
                const float2 v = pin[k];
                sr = fmaf(u.x, v.x, sr); sr = fmaf(-u.y, v.y, sr);
                si = fmaf(u.x, v.y, si); si = fmaf(u.y, v.x, si);
            }
            sr += __shfl_xor_sync(0xffffffffu, sr, 1);
            sr += __shfl_xor_sync(0xffffffffu, sr, 2);
            si += __shfl_xor_sync(0xffffffffu, si, 1);
            si += __shfl_xor_sync(0xffffffffu, si, 2);
            if (part == 0) pout[row] = make_float2(sr, si);
        }
        __syncthreads();
        { float2* t = pin; pin = pout; pout = t; }
    }

    if (tid < DIM) {
        const float2 v = pin[tid];
        out[(size_t)b * DIM + tid] = fmaf(v.x, v.x, v.y * v.y) + bias[tid];
    }
}

extern "C" void kernel_launch(void* const* d_in, const int* in_sizes, int n_in,
                              void* d_out, int out_size)
{
    const float* x      = (const float*)d_in[0];   // [512, 4000]
    const float* weight = (const float*)d_in[1];   // [4, 4095]
    const float* bias   = (const float*)d_in[2];   // [64]
    float* out = (float*)d_out;                    // [512, 64]

    const int B     = in_sizes[0] / 4000;
    const int nreps = in_sizes[1] / (NPAULI - 1);

    const size_t smem = (size_t)10 * PL * sizeof(float);   // 174,080 B
    cudaFuncSetAttribute(build_kernel,
                         cudaFuncAttributeMaxDynamicSharedMemorySize, (int)smem);

    build_kernel<<<nreps + B, NTHREADS, smem>>>(x, weight, nreps);
    circuit_kernel<<<B, NTHREADS>>>(bias, out, nreps);
}

// round 4
// speedup vs baseline: 1.6729x; 1.0526x over previous
#include <cuda_runtime.h>

// ---------------------------------------------------------------------------
// DataReUploadingLinear: 6-qubit data re-uploading circuit.
// Round 3: 512 threads/CTA (2x4 thread tile) for 4 warps/SMSP,
// circuit fused into build kernel via flag spin (Up blocks release, data
// blocks acquire), LDS.128 X loads, negative-accumulator trick (fewer MOVs).
// ---------------------------------------------------------------------------

#define DIM      64
#define NPAULI   4096
#define S        68                  // smem row stride: 17 x float4, rows 16B-aligned
#define PL       (64 * S)            // plane size in floats (4352)
#define NTHREADS 512
#define INV_SCALE (1.0f / 256.0f)    // 1 / 2^s, s = 8

typedef unsigned long long u64;

__device__ float2 g_Up[4][DIM * DIM];   // parameter unitaries [i*64+k]
__device__ int    g_flag;               // count of finished Up blocks

__device__ __forceinline__ u64 pk2(float lo, float hi) {
    u64 r; asm("mov.b64 %0, {%1, %2};" : "=l"(r) : "f"(lo), "f"(hi)); return r;
}
__device__ __forceinline__ u64 f2fma(u64 a, u64 b, u64 c) {
    u64 d; asm("fma.rn.f32x2 %0, %1, %2, %3;" : "=l"(d) : "l"(a), "l"(b), "l"(c));
    return d;
}
// a - b, done scalar-wise (safe on all ptxas)
__device__ __forceinline__ u64 f2sub(u64 a, u64 b) {
    float al, ah, bl, bh;
    asm("mov.b64 {%0, %1}, %2;" : "=f"(al), "=f"(ah) : "l"(a));
    asm("mov.b64 {%0, %1}, %2;" : "=f"(bl), "=f"(bh) : "l"(b));
    return pk2(al - bl, ah - bh);
}

// Z = [G(A)] + X*Y, complex 64x64 in smem (separate re/im planes, stride S).
// G = c0*I + c1*A + c2*A2 when WITHG. Thread tile 2 rows x 4 cols, f32x2
// packed over column pairs. 512 threads: ty=tid>>4 (32 row-groups of 2),
// tx=tid&15 (16 col-groups of 4).
template <bool WITHG>
__device__ __forceinline__ void cmm(
    const float* __restrict__ Xr, const float* __restrict__ Xi,
    const float* __restrict__ Yr, const float* __restrict__ Yi,
    float* __restrict__ Zr, float* __restrict__ Zi,
    const float* __restrict__ Ar, const float* __restrict__ Ai,
    const float* __restrict__ A2r, const float* __restrict__ A2i,
    float c0, float c1, float c2)
{
    const int tid = threadIdx.x;
    const int ty = tid >> 4, tx = tid & 15;
    const int i0 = ty * 2, j0 = tx * 4;

    u64 crp[2][2], crn[2][2], cim[2][2];
#pragma unroll
    for (int a = 0; a < 2; a++)
#pragma unroll
        for (int p = 0; p < 2; p++) {
            if (WITHG) {
                const int i = i0 + a, j = j0 + 2 * p;
                const int o0 = i * S + j, o1 = o0 + 1;
                float g0r = c1 * Ar[o0] + c2 * A2r[o0] + ((i == j)     ? c0 : 0.f);
                float g1r = c1 * Ar[o1] + c2 * A2r[o1] + ((i == j + 1) ? c0 : 0.f);
                float g0i = c1 * Ai[o0] + c2 * A2i[o0];
                float g1i = c1 * Ai[o1] + c2 * A2i[o1];
                crp[a][p] = pk2(g0r, g1r);
                cim[a][p] = pk2(g0i, g1i);
            } else {
                crp[a][p] = 0ull; cim[a][p] = 0ull;
            }
            crn[a][p] = 0ull;
        }

#pragma unroll 2
    for (int k0 = 0; k0 < 64; k0 += 4) {
        // X: LDS.128 over 4 consecutive k (broadcast within half-warp)
        float4 xr4[2], xi4[2];
#pragma unroll
        for (int a = 0; a < 2; a++) {
            xr4[a] = *(const float4*)&Xr[(i0 + a) * S + k0];
            xi4[a] = *(const float4*)&Xi[(i0 + a) * S + k0];
        }
#pragma unroll
        for (int kk = 0; kk < 4; kk++) {
            // Y row k0+kk: LDS.128 re + LDS.128 im, used as packed col pairs
            const ulonglong2 r2 = *(const ulonglong2*)&Yr[(k0 + kk) * S + j0];
            const ulonglong2 q2 = *(const ulonglong2*)&Yi[(k0 + kk) * S + j0];
            const u64 yr[2] = { r2.x, r2.y };
            const u64 yi[2] = { q2.x, q2.y };
#pragma unroll
            for (int a = 0; a < 2; a++) {
                const float xr = (kk == 0) ? xr4[a].x : (kk == 1) ? xr4[a].y
                               : (kk == 2) ? xr4[a].z : xr4[a].w;
                const float xi = (kk == 0) ? xi4[a].x : (kk == 1) ? xi4[a].y
                               : (kk == 2) ? xi4[a].z : xi4[a].w;
                const u64 xrr = pk2(xr, xr);
                const u64 xii = pk2(xi, xi);
#pragma unroll
                for (int p = 0; p < 2; p++) {
                    crp[a][p] = f2fma(xrr, yr[p], crp[a][p]);
                    crn[a][p] = f2fma(xii, yi[p], crn[a][p]);
                    cim[a][p] = f2fma(xrr, yi[p], cim[a][p]);
                    cim[a][p] = f2fma(xii, yr[p], cim[a][p]);
                }
            }
        }
    }

#pragma unroll
    for (int a = 0; a < 2; a++)
#pragma unroll
        for (int p = 0; p < 2; p++) {
            *(u64*)&Zr[(i0 + a) * S + j0 + 2 * p] = f2sub(crp[a][p], crn[a][p]);
            *(u64*)&Zi[(i0 + a) * S + j0 + 2 * p] = cim[a][p];
        }
}

__global__ void reset_kernel() { g_flag = 0; }

// blockIdx < nreps: build Up[blk] -> g_Up, release flag.
// else: build Ud for sample (blk - nreps), wait for flag, run circuit, write out.
__global__ __launch_bounds__(NTHREADS)
void build_kernel(const float* __restrict__ x,
                  const float* __restrict__ weight,
                  const float* __restrict__ bias,
                  float* __restrict__ out,
                  int nreps)
{
    extern __shared__ float sm[];
    float* Ar  = sm + 0 * PL;  float* Ai  = sm + 1 * PL;
    float* A2r = sm + 2 * PL;  float* A2i = sm + 3 * PL;
    float* A3r = sm + 4 * PL;  float* A3i = sm + 5 * PL;
    float* Br  = sm + 6 * PL;  float* Bi  = sm + 7 * PL;
    float* Cr  = sm + 8 * PL;  float* Ci  = sm + 9 * PL;
    __shared__ float2 psiA[DIM], psiB[DIM];

    const int tid = threadIdx.x;
    const int blk = blockIdx.x;
    const bool is_param = (blk < nreps);

    // ---- 1. Pauli coefficients (padded to 4096) into Br[0..4095] ----
    if (is_param) {
        const float* wrow = weight + (size_t)blk * (NPAULI - 1);
        for (int p = tid; p < NPAULI; p += NTHREADS)
            Br[p] = (p == 0) ? 0.f : wrow[p - 1];      // identity excluded
    } else {
        const float* xrow = x + (size_t)(blk - nreps) * 4000;
        for (int p = tid; p < NPAULI; p += NTHREADS)
            Br[p] = (p < 4000) ? xrow[p] : 0.f;
    }
    __syncthreads();

    // ---- 2. D[m][t] = coef(p(m,t)) * (-i)^popc(t&m) ----
    for (int idx = tid; idx < NPAULI; idx += NTHREADS) {
        const int m = idx >> 6, t = idx & 63;
        const int mt = m ^ t;
        int p = 0;
#pragma unroll
        for (int k = 0; k < 6; k++)
            p |= (((mt >> k) & 1) << (2 * k)) | (((t >> k) & 1) << (2 * k + 1));
        const float v = Br[p];
        const int c = __popc(t & m) & 3;   // (-i)^c
        float re, im;
        switch (c) {
            case 0:  re =  v; im = 0.f; break;
            case 1:  re = 0.f; im = -v; break;
            case 2:  re = -v; im = 0.f; break;
            default: re = 0.f; im =  v; break;
        }
        Cr[idx] = re; Ci[idx] = im;
    }
    __syncthreads();

    // ---- 3. 64-pt WHT over t for each m ----
    for (int s = 0; s < 6; s++) {
        const int half = 1 << s;
        for (int n = tid; n < 2048; n += NTHREADS) {
            const int m = n >> 5, r = n & 31;
            const int t0 = ((r >> s) << (s + 1)) | (r & (half - 1));
            const int a0 = m * 64 + t0, a1 = a0 + half;
            const float ur = Cr[a0], ui = Ci[a0];
            const float vr = Cr[a1], vi = Ci[a1];
            Cr[a0] = ur + vr; Ci[a0] = ui + vi;
            Cr[a1] = ur - vr; Ci[a1] = ui - vi;
        }
        __syncthreads();
    }

    // ---- 4. A = -i*H/2^s :  H[i][i^m] = W[m][i] ----
    for (int idx = tid; idx < NPAULI; idx += NTHREADS) {
        const int m = idx >> 6, i = idx & 63;
        const int j = i ^ m;
        const float hr = Cr[m * 64 + i], hi = Ci[m * 64 + i];
        Ar[i * S + j] =  hi * INV_SCALE;   // -i*(hr+i*hi) = hi - i*hr
        Ai[i * S + j] = -hr * INV_SCALE;
    }
    __syncthreads();

    // ---- 5. powers A2, A3 ----
    cmm<false>(Ar, Ai, Ar, Ai, A2r, A2i, Ar, Ai, A2r, A2i, 0, 0, 0);
    __syncthreads();
    cmm<false>(A2r, A2i, Ar, Ai, A3r, A3i, Ar, Ai, A2r, A2i, 0, 0, 0);
    __syncthreads();

    // ---- 6. degree-11 PS: E = G0 + A3*(G1 + A3*(G2 + A3*G3)) ----
    {   // B = G3 = I/9! + A/10! + A2/11!
        const float c0 = 2.75573192e-6f, c1 = 2.75573192e-7f, c2 = 2.50521084e-8f;
        for (int idx = tid; idx < NPAULI; idx += NTHREADS) {
            const int i = idx >> 6, j = idx & 63;
            const int o = i * S + j;
            float gr = c1 * Ar[o] + c2 * A2r[o];
            float gi = c1 * Ai[o] + c2 * A2i[o];
            if (i == j) gr += c0;
            Br[o] = gr; Bi[o] = gi;
        }
    }
    __syncthreads();
    // C = G2 + A3*B   (I/6! + A/7! + A2/8!)
    cmm<true>(A3r, A3i, Br, Bi, Cr, Ci, Ar, Ai, A2r, A2i,
              1.38888889e-3f, 1.98412698e-4f, 2.48015873e-5f);
    __syncthreads();
    // B = G1 + A3*C   (I/3! + A/4! + A2/5!)
    cmm<true>(A3r, A3i, Cr, Ci, Br, Bi, Ar, Ai, A2r, A2i,
              1.f / 6.f, 1.f / 24.f, 1.f / 120.f);
    __syncthreads();
    // C = G0 + A3*B   (I + A + A2/2)
    cmm<true>(A3r, A3i, Br, Bi, Cr, Ci, Ar, Ai, A2r, A2i,
              1.f, 1.f, 0.5f);
    __syncthreads();

    // ---- 7. 8 squarings, ping-pong C <-> B (ends in C) ----
    float *qr = Cr, *qi = Ci, *pr = Br, *pi = Bi;
#pragma unroll 1
    for (int q = 0; q < 8; q++) {
        cmm<false>(qr, qi, qr, qi, pr, pi, Ar, Ai, A2r, A2i, 0, 0, 0);
        __syncthreads();
        float* t;
        t = qr; qr = pr; pr = t;
        t = qi; qi = pi; pi = t;
    }

    // ---- 8a. parameter blocks: publish Up and signal ----
    if (is_param) {
        for (int idx = tid; idx < DIM * DIM; idx += NTHREADS) {
            const int i = idx >> 6, j = idx & 63;
            g_Up[blk][idx] = make_float2(qr[i * S + j], qi[i * S + j]);
        }
        __threadfence();               // release g_Up before flag bump
        __syncthreads();
        if (tid == 0) atomicAdd(&g_flag, 1);
        return;
    }

    // ---- 8b. data blocks: wait for all Up, then run circuit in-CTA ----
    if (tid == 0) {
        int v;
        do {
            asm volatile("ld.global.acquire.gpu.b32 %0, [%1];"
                         : "=r"(v) : "l"(&g_flag));
            if (v < nreps) __nanosleep(64);
        } while (v < nreps);
    }
    __threadfence();
    if (tid < DIM) psiA[tid] = make_float2(tid == 0 ? 1.f : 0.f, 0.f);
    __syncthreads();

    if (tid < 256) {
        float2* pin = psiA;
        float2* pout = psiB;
        const int row = tid >> 2, part = tid & 3;
        const int k0 = part * 16;

        for (int r = 0; r < nreps; r++) {
            {   // pout = Ud * pin   (Ud lives in smem planes qr/qi)
                float sr = 0.f, si = 0.f;
#pragma unroll
                for (int k = k0; k < k0 + 16; k++) {
                    const float mr = qr[row * S + k], mi = qi[row * S + k];
                    const float2 v = pin[k];
                    sr = fmaf(mr, v.x, sr); sr = fmaf(-mi, v.y, sr);
                    si = fmaf(mr, v.y, si); si = fmaf(mi, v.x, si);
                }
                sr += __shfl_xor_sync(0xffffffffu, sr, 1);
                sr += __shfl_xor_sync(0xffffffffu, sr, 2);
                si += __shfl_xor_sync(0xffffffffu, si, 1);
                si += __shfl_xor_sync(0xffffffffu, si, 2);
                if (part == 0) pout[row] = make_float2(sr, si);
            }
            __syncwarp();
            asm volatile("bar.sync 1, 256;" ::: "memory");
            { float2* t = pin; pin = pout; pout = t; }

            {   // pout = Up[r] * pin
                const float2* U = g_Up[r];
                float sr = 0.f, si = 0.f;
#pragma unroll
                for (int k = k0; k < k0 + 16; k++) {
                    const float2 u = U[row * DIM + k];
                    const float2 v = pin[k];
                    sr = fmaf(u.x, v.x, sr); sr = fmaf(-u.y, v.y, sr);
                    si = fmaf(u.x, v.y, si); si = fmaf(u.y, v.x, si);
                }
                sr += __shfl_xor_sync(0xffffffffu, sr, 1);
                sr += __shfl_xor_sync(0xffffffffu, sr, 2);
                si += __shfl_xor_sync(0xffffffffu, si, 1);
                si += __shfl_xor_sync(0xffffffffu, si, 2);
                if (part == 0) pout[row] = make_float2(sr, si);
            }
            __syncwarp();
            asm volatile("bar.sync 1, 256;" ::: "memory");
            { float2* t = pin; pin = pout; pout = t; }
        }

        if (tid < DIM) {
            const float2 v = pin[tid];
            out[(size_t)(blk - nreps) * DIM + tid] =
                fmaf(v.x, v.x, v.y * v.y) + bias[tid];
        }
    }
}

extern "C" void kernel_launch(void* const* d_in, const int* in_sizes, int n_in,
                              void* d_out, int out_size)
{
    const float* x      = (const float*)d_in[0];   // [512, 4000]
    const float* weight = (const float*)d_in[1];   // [4, 4095]
    const float* bias   = (const float*)d_in[2];   // [64]
    float* out = (float*)d_out;                    // [512, 64]

    const int B     = in_sizes[0] / 4000;
    const int nreps = in_sizes[1] / (NPAULI - 1);

    const size_t smem = (size_t)10 * PL * sizeof(float);   // 174,080 B
    cudaFuncSetAttribute(build_kernel,
                         cudaFuncAttributeMaxDynamicSharedMemorySize, (int)smem);

    reset_kernel<<<1, 1>>>();
    build_kernel<<<nreps + B, NTHREADS, smem>>>(x, weight, bias, out, nreps);
}